// round 7
// baseline (speedup 1.0000x reference)
#include <cuda_runtime.h>
#include <cuda_fp16.h>
#include <cstdint>

// ---------------------------------------------------------------------------
// RoutedBitLinear: out[M,N] = x[M,K] @ (signs * blended_scales)[N,K]^T
// M=8192, N=4096, K=4096, group_size=128, P=8.
// mma.sync.m16n8k16 f16 path (tcgen05 unavailable: harness PTX target sm_103).
// R6: like R5 (CTA 128x128, 4 warps, warp tile 64x64, 2 CTAs/SM) but BK=64
// with 3 stages: halves the per-iteration sync/wait/LDSM-head overhead that
// accounted for the ~22% tensor idle in R5 (128 -> 64 mainloop iterations).
// Stage = two R5-format 16KB sub-stages, addressing unchanged.
// ---------------------------------------------------------------------------

#define DM 8192
#define DN 4096
#define DK 4096
#define NGROUPS (DN * DK / 128)   // 131072

#define BM 128
#define BN 128
#define BK 64                      // halves per k-chunk (2 sub-tiles of 32)
#define STAGES 3
#define NITER (DK / BK)            // 64
#define SUB_A_BYTES (BM * 32 * 2)  // 8192 (per 32-k sub-tile)
#define SUB_BYTES (2 * SUB_A_BYTES)         // 16384 (A+B sub-stage)
#define STAGE_BYTES (2 * SUB_BYTES)         // 32768
#define SMEM_TOTAL (STAGES * STAGE_BYTES)   // 98304 -> 2 CTAs/SM (192KB/SM)

// Scratch (static device globals: allocation-free per harness rules)
__device__ __align__(256) __half g_Wh[(size_t)DN * DK];   // 32 MB
__device__ __align__(256) __half g_Xh[(size_t)DM * DK];   // 64 MB
__device__ float g_blend[NGROUPS];

// ------------------------------ helpers ------------------------------------
__device__ __forceinline__ uint32_t smem_u32(const void* p) {
    return (uint32_t)__cvta_generic_to_shared(p);
}
__device__ __forceinline__ void cp_async16(uint32_t dst, const void* src) {
    asm volatile("cp.async.cg.shared.global [%0], [%1], 16;" :: "r"(dst), "l"(src));
}
__device__ __forceinline__ void cp_commit() {
    asm volatile("cp.async.commit_group;");
}
template <int Npend>
__device__ __forceinline__ void cp_wait() {
    asm volatile("cp.async.wait_group %0;" :: "n"(Npend));
}
__device__ __forceinline__ void ldmx4(uint32_t* d, uint32_t addr) {
    asm volatile("ldmatrix.sync.aligned.m8n8.x4.shared.b16 {%0,%1,%2,%3}, [%4];"
                 : "=r"(d[0]), "=r"(d[1]), "=r"(d[2]), "=r"(d[3]) : "r"(addr));
}
__device__ __forceinline__ void mma16816(float* c, const uint32_t* a, const uint32_t* b) {
    asm volatile(
        "mma.sync.aligned.m16n8k16.row.col.f32.f16.f16.f32 "
        "{%0,%1,%2,%3}, {%4,%5,%6,%7}, {%8,%9}, {%0,%1,%2,%3};"
        : "+f"(c[0]), "+f"(c[1]), "+f"(c[2]), "+f"(c[3])
        : "r"(a[0]), "r"(a[1]), "r"(a[2]), "r"(a[3]), "r"(b[0]), "r"(b[1]));
}

// ------------------------------ prep kernels -------------------------------
__global__ void blend_kernel(const float* __restrict__ ps, const float* __restrict__ rt) {
    int g = blockIdx.x * 256 + threadIdx.x;
    float acc = 0.f;
#pragma unroll
    for (int p = 0; p < 8; p++)
        acc = fmaf(rt[p], ps[(size_t)p * NGROUPS + g], acc);
    g_blend[g] = acc;
}

__global__ void weight_kernel(const float* __restrict__ signs) {
    size_t base = ((size_t)blockIdx.x * 256 + threadIdx.x) * 8;
    float s = g_blend[base >> 7];  // flat index >> 7 == o*32 + i/128
    float4 a = *(const float4*)(signs + base);
    float4 b = *(const float4*)(signs + base + 4);
    union { __half2 h[4]; uint4 u; } pk;
    pk.h[0] = __floats2half2_rn(a.x * s, a.y * s);
    pk.h[1] = __floats2half2_rn(a.z * s, a.w * s);
    pk.h[2] = __floats2half2_rn(b.x * s, b.y * s);
    pk.h[3] = __floats2half2_rn(b.z * s, b.w * s);
    *(uint4*)(g_Wh + base) = pk.u;
}

__global__ void xconv_kernel(const float* __restrict__ x) {
    size_t base = ((size_t)blockIdx.x * 256 + threadIdx.x) * 8;
    float4 a = *(const float4*)(x + base);
    float4 b = *(const float4*)(x + base + 4);
    union { __half2 h[4]; uint4 u; } pk;
    pk.h[0] = __floats2half2_rn(a.x, a.y);
    pk.h[1] = __floats2half2_rn(a.z, a.w);
    pk.h[2] = __floats2half2_rn(b.x, b.y);
    pk.h[3] = __floats2half2_rn(b.z, b.w);
    *(uint4*)(g_Xh + base) = pk.u;
}

// ------------------------------ GEMM kernel --------------------------------
// Each 16KB sub-stage: A[128 rows][32 halves] then B[128 rows][32 halves],
// 64B rows XOR-swizzled in 16B chunks: c ^= (row>>1)&3. Conflict-free for
// cp.async writes and all ldmatrix phases.
__global__ void __launch_bounds__(128, 2) gemm_kernel(float* __restrict__ out) {
    extern __shared__ char smem_raw[];
    const uint32_t sbase = smem_u32(smem_raw);
    const int tid = threadIdx.x;
    const int wid = tid >> 5;
    const int lane = tid & 31;
    const int warp_m = wid & 1;    // 2 warps along M (64 rows each)
    const int warp_n = wid >> 1;   // 2 warps along N (64 cols each)

    // rasterize for L2 reuse
    const int num_n = DN / BN;     // 32
    const int GROUP_M = 16;
    int bid = blockIdx.x;
    int tpg = GROUP_M * num_n;     // 512
    int group = bid / tpg;
    int rem = bid - group * tpg;
    int mt_blk = group * GROUP_M + (rem % GROUP_M);
    int nt_blk = rem / GROUP_M;
    const size_t m0 = (size_t)mt_blk * BM;
    const size_t n0 = (size_t)nt_blk * BN;

    const __half* gA = g_Xh + m0 * DK;
    const __half* gB = g_Wh + n0 * DK;

    auto load_stage = [&](int s, int kc) {
        uint32_t base = sbase + s * STAGE_BYTES;
        int k0 = kc * BK;
#pragma unroll
        for (int h = 0; h < 2; h++) {
            uint32_t sub = base + h * SUB_BYTES;
            int kh = k0 + h * 32;
#pragma unroll
            for (int j = 0; j < 4; j++) {      // A then B: 128 rows x 4 chunks
                int i = tid + j * 128;         // 0..511
                int row = i >> 2;
                int c = i & 3;
                uint32_t off = (uint32_t)(row * 64 + ((c ^ ((row >> 1) & 3)) * 16));
                cp_async16(sub + off, gA + (size_t)row * DK + kh + c * 8);
                cp_async16(sub + SUB_A_BYTES + off, gB + (size_t)row * DK + kh + c * 8);
            }
        }
    };

    // per-thread ldmatrix address components (xor term constant across mt/h
    // tiles: tile strides are 16 rows, and (16>>1)&3 == 0)
    const int rowA = warp_m * 64 + (lane & 15);
    const int xa = (rowA >> 1) & 3;
    const uint32_t offA = (uint32_t)(rowA * 64);
    const int rowB = warp_n * 64 + ((lane >> 4) << 3) + (lane & 7);
    const int xb = (rowB >> 1) & 3;
    const uint32_t offB = (uint32_t)(rowB * 64);

    float acc[4][8][4];
#pragma unroll
    for (int mt = 0; mt < 4; mt++)
#pragma unroll
        for (int nt = 0; nt < 8; nt++)
#pragma unroll
            for (int r = 0; r < 4; r++) acc[mt][nt][r] = 0.f;

    // prologue: stages 0..1
#pragma unroll
    for (int s = 0; s < STAGES - 1; s++) { load_stage(s, s); cp_commit(); }

    for (int it = 0; it < NITER; it++) {
        cp_wait<STAGES - 2>();
        __syncthreads();

        int kc = it + STAGES - 1;
        int sload = kc;  // mod 3 below
        if (kc < NITER) load_stage(sload % STAGES, kc);
        cp_commit();

        const uint32_t stg = sbase + (it % STAGES) * STAGE_BYTES;
#pragma unroll
        for (int half = 0; half < 2; half++) {
            const uint32_t stA = stg + half * SUB_BYTES;
            const uint32_t stB = stA + SUB_A_BYTES;
#pragma unroll
            for (int s16 = 0; s16 < 2; s16++) {
                uint32_t a[4][4];
                uint32_t b[8][2];
                const int cA = (s16 * 2 + (lane >> 4)) ^ xa;
#pragma unroll
                for (int mt = 0; mt < 4; mt++)
                    ldmx4(a[mt], stA + offA + mt * 1024 + cA * 16);
                const int cB = (s16 * 2 + ((lane >> 3) & 1)) ^ xb;
#pragma unroll
                for (int h = 0; h < 4; h++) {  // 4 x (16 rows of B) = 64 cols
                    uint32_t r[4];
                    ldmx4(r, stB + offB + h * 1024 + cB * 16);
                    b[h * 2 + 0][0] = r[0]; b[h * 2 + 0][1] = r[1];
                    b[h * 2 + 1][0] = r[2]; b[h * 2 + 1][1] = r[3];
                }
#pragma unroll
                for (int mt = 0; mt < 4; mt++)
#pragma unroll
                    for (int nt = 0; nt < 8; nt++)
                        mma16816(acc[mt][nt], a[mt], b[nt]);
            }
        }
    }

    // epilogue: direct global stores (float2 per fragment pair)
    float* op = out + m0 * DN + n0;
#pragma unroll
    for (int mt = 0; mt < 4; mt++) {
        int r0 = warp_m * 64 + mt * 16 + (lane >> 2);
#pragma unroll
        for (int nt = 0; nt < 8; nt++) {
            int col = warp_n * 64 + nt * 8 + (lane & 3) * 2;
            float2* p0 = (float2*)(op + (size_t)r0 * DN + col);
            float2* p1 = (float2*)(op + (size_t)(r0 + 8) * DN + col);
            *p0 = make_float2(acc[mt][nt][0], acc[mt][nt][1]);
            *p1 = make_float2(acc[mt][nt][2], acc[mt][nt][3]);
        }
    }
}

// ------------------------------ launch -------------------------------------
extern "C" void kernel_launch(void* const* d_in, const int* in_sizes, int n_in,
                              void* d_out, int out_size) {
    (void)in_sizes; (void)n_in; (void)out_size;
    const float* x       = (const float*)d_in[0];
    const float* signs   = (const float*)d_in[1];
    const float* ps      = (const float*)d_in[2];
    const float* routing = (const float*)d_in[3];
    float* out = (float*)d_out;

    cudaFuncSetAttribute(gemm_kernel, cudaFuncAttributeMaxDynamicSharedMemorySize,
                         SMEM_TOTAL);

    blend_kernel<<<NGROUPS / 256, 256>>>(ps, routing);
    weight_kernel<<<(int)(((size_t)DN * DK / 8) / 256), 256>>>(signs);
    xconv_kernel<<<(int)(((size_t)DM * DK / 8) / 256), 256>>>(x);
    gemm_kernel<<<(DM / BM) * (DN / BN), 128, SMEM_TOTAL>>>(out);
}

// round 8
// speedup vs baseline: 1.0515x; 1.0515x over previous
#include <cuda_runtime.h>
#include <cuda_fp16.h>
#include <cstdint>

// ---------------------------------------------------------------------------
// RoutedBitLinear: out[M,N] = x[M,K] @ (signs * blended_scales)[N,K]^T
// M=8192, N=4096, K=4096, group_size=128, P=8.
// mma.sync.m16n8k16 f16 path (tcgen05 unavailable: harness PTX target sm_103).
// R8 = R5 (CTA 128x128, 4 warps, warp tile 64x64, BK=32, 4 stages, 2 CTAs/SM)
// + reordered iteration body:
//   (1) all 16 ldmatrix issued up-front (both k16 halves) -> single LDSM
//       dependency head per iter, rest overlap with MMAs;
//   (2) cp.async burst issued AFTER ldmatrix -> LDSM no longer queues behind
//       cp.async in the LSU (the R6 regression mechanism).
// ---------------------------------------------------------------------------

#define DM 8192
#define DN 4096
#define DK 4096
#define NGROUPS (DN * DK / 128)   // 131072

#define BM 128
#define BN 128
#define BK 32                      // halves per k-chunk
#define STAGES 4
#define NITER (DK / BK)            // 128
#define TILE_A_BYTES (BM * BK * 2) // 8192
#define STAGE_BYTES (2 * TILE_A_BYTES)      // 16384 (A + B)
#define SMEM_TOTAL (STAGES * STAGE_BYTES)   // 65536 -> 2 CTAs/SM

// Scratch (static device globals: allocation-free per harness rules)
__device__ __align__(256) __half g_Wh[(size_t)DN * DK];   // 32 MB
__device__ __align__(256) __half g_Xh[(size_t)DM * DK];   // 64 MB
__device__ float g_blend[NGROUPS];

// ------------------------------ helpers ------------------------------------
__device__ __forceinline__ uint32_t smem_u32(const void* p) {
    return (uint32_t)__cvta_generic_to_shared(p);
}
__device__ __forceinline__ void cp_async16(uint32_t dst, const void* src) {
    asm volatile("cp.async.cg.shared.global [%0], [%1], 16;" :: "r"(dst), "l"(src));
}
__device__ __forceinline__ void cp_commit() {
    asm volatile("cp.async.commit_group;");
}
template <int Npend>
__device__ __forceinline__ void cp_wait() {
    asm volatile("cp.async.wait_group %0;" :: "n"(Npend));
}
__device__ __forceinline__ void ldmx4(uint32_t* d, uint32_t addr) {
    asm volatile("ldmatrix.sync.aligned.m8n8.x4.shared.b16 {%0,%1,%2,%3}, [%4];"
                 : "=r"(d[0]), "=r"(d[1]), "=r"(d[2]), "=r"(d[3]) : "r"(addr));
}
__device__ __forceinline__ void mma16816(float* c, const uint32_t* a, const uint32_t* b) {
    asm volatile(
        "mma.sync.aligned.m16n8k16.row.col.f32.f16.f16.f32 "
        "{%0,%1,%2,%3}, {%4,%5,%6,%7}, {%8,%9}, {%0,%1,%2,%3};"
        : "+f"(c[0]), "+f"(c[1]), "+f"(c[2]), "+f"(c[3])
        : "r"(a[0]), "r"(a[1]), "r"(a[2]), "r"(a[3]), "r"(b[0]), "r"(b[1]));
}

// ------------------------------ prep kernels -------------------------------
__global__ void blend_kernel(const float* __restrict__ ps, const float* __restrict__ rt) {
    int g = blockIdx.x * 256 + threadIdx.x;
    float acc = 0.f;
#pragma unroll
    for (int p = 0; p < 8; p++)
        acc = fmaf(rt[p], ps[(size_t)p * NGROUPS + g], acc);
    g_blend[g] = acc;
}

__global__ void weight_kernel(const float* __restrict__ signs) {
    size_t base = ((size_t)blockIdx.x * 256 + threadIdx.x) * 8;
    float s = g_blend[base >> 7];  // flat index >> 7 == o*32 + i/128
    float4 a = *(const float4*)(signs + base);
    float4 b = *(const float4*)(signs + base + 4);
    union { __half2 h[4]; uint4 u; } pk;
    pk.h[0] = __floats2half2_rn(a.x * s, a.y * s);
    pk.h[1] = __floats2half2_rn(a.z * s, a.w * s);
    pk.h[2] = __floats2half2_rn(b.x * s, b.y * s);
    pk.h[3] = __floats2half2_rn(b.z * s, b.w * s);
    *(uint4*)(g_Wh + base) = pk.u;
}

__global__ void xconv_kernel(const float* __restrict__ x) {
    size_t base = ((size_t)blockIdx.x * 256 + threadIdx.x) * 8;
    float4 a = *(const float4*)(x + base);
    float4 b = *(const float4*)(x + base + 4);
    union { __half2 h[4]; uint4 u; } pk;
    pk.h[0] = __floats2half2_rn(a.x, a.y);
    pk.h[1] = __floats2half2_rn(a.z, a.w);
    pk.h[2] = __floats2half2_rn(b.x, b.y);
    pk.h[3] = __floats2half2_rn(b.z, b.w);
    *(uint4*)(g_Xh + base) = pk.u;
}

// ------------------------------ GEMM kernel --------------------------------
// smem per stage: A[128 rows][32 halves] then B[128 rows][32 halves], 64B rows
// XOR-swizzled in 16B chunks: c ^= (row>>1)&3. Conflict-free for cp.async
// writes and all ldmatrix phases.
__global__ void __launch_bounds__(128, 2) gemm_kernel(float* __restrict__ out) {
    extern __shared__ char smem_raw[];
    const uint32_t sbase = smem_u32(smem_raw);
    const int tid = threadIdx.x;
    const int wid = tid >> 5;
    const int lane = tid & 31;
    const int warp_m = wid & 1;    // 2 warps along M (64 rows each)
    const int warp_n = wid >> 1;   // 2 warps along N (64 cols each)

    // rasterize for L2 reuse
    const int num_n = DN / BN;     // 32
    const int GROUP_M = 16;
    int bid = blockIdx.x;
    int tpg = GROUP_M * num_n;     // 512
    int group = bid / tpg;
    int rem = bid - group * tpg;
    int mt_blk = group * GROUP_M + (rem % GROUP_M);
    int nt_blk = rem / GROUP_M;
    const size_t m0 = (size_t)mt_blk * BM;
    const size_t n0 = (size_t)nt_blk * BN;

    const __half* gA = g_Xh + m0 * DK;
    const __half* gB = g_Wh + n0 * DK;

    auto load_stage = [&](int s, int kc) {
        uint32_t base = sbase + s * STAGE_BYTES;
        int k0 = kc * BK;
#pragma unroll
        for (int j = 0; j < 4; j++) {          // A then B: 128 rows x 4 chunks each
            int i = tid + j * 128;             // 0..511
            int row = i >> 2;
            int c = i & 3;
            uint32_t off = (uint32_t)(row * 64 + ((c ^ ((row >> 1) & 3)) * 16));
            cp_async16(base + off, gA + (size_t)row * DK + k0 + c * 8);
            cp_async16(base + TILE_A_BYTES + off, gB + (size_t)row * DK + k0 + c * 8);
        }
    };

    // per-thread ldmatrix address components (xor term constant across mt/h
    // tiles: tile strides are 16 rows, and (16>>1)&3 == 0)
    const int rowA = warp_m * 64 + (lane & 15);
    const int xa = (rowA >> 1) & 3;
    const uint32_t offA = (uint32_t)(rowA * 64);
    const int rowB = warp_n * 64 + ((lane >> 4) << 3) + (lane & 7);
    const int xb = (rowB >> 1) & 3;
    const uint32_t offB = (uint32_t)(rowB * 64);

    float acc[4][8][4];
#pragma unroll
    for (int mt = 0; mt < 4; mt++)
#pragma unroll
        for (int nt = 0; nt < 8; nt++)
#pragma unroll
            for (int r = 0; r < 4; r++) acc[mt][nt][r] = 0.f;

    // prologue: stages 0..2
#pragma unroll
    for (int s = 0; s < STAGES - 1; s++) { load_stage(s, s); cp_commit(); }

    for (int it = 0; it < NITER; it++) {
        cp_wait<STAGES - 2>();
        __syncthreads();

        const uint32_t stA = sbase + (it & (STAGES - 1)) * STAGE_BYTES;
        const uint32_t stB = stA + TILE_A_BYTES;

        // (1) all fragment loads first: one LDSM dependency head per iter
        uint32_t a[2][4][4];
        uint32_t b[2][8][2];
#pragma unroll
        for (int s16 = 0; s16 < 2; s16++) {
            const int cA = (s16 * 2 + (lane >> 4)) ^ xa;
#pragma unroll
            for (int mt = 0; mt < 4; mt++)
                ldmx4(a[s16][mt], stA + offA + mt * 1024 + cA * 16);
            const int cB = (s16 * 2 + ((lane >> 3) & 1)) ^ xb;
#pragma unroll
            for (int h = 0; h < 4; h++)       // writes b[s16][2h],[2h+1]
                ldmx4(&b[s16][h * 2][0], stB + offB + h * 1024 + cB * 16);
        }

        // (2) cp.async burst after LDSM issue: no LSU queueing ahead of them
        int kc = it + STAGES - 1;
        if (kc < NITER) load_stage(kc & (STAGES - 1), kc);
        cp_commit();

        // 64 MMAs; LDSM completions overlap
#pragma unroll
        for (int s16 = 0; s16 < 2; s16++)
#pragma unroll
            for (int mt = 0; mt < 4; mt++)
#pragma unroll
                for (int nt = 0; nt < 8; nt++)
                    mma16816(acc[mt][nt], a[s16][mt], b[s16][nt]);
    }

    // epilogue: direct global stores (float2 per fragment pair)
    float* op = out + m0 * DN + n0;
#pragma unroll
    for (int mt = 0; mt < 4; mt++) {
        int r0 = warp_m * 64 + mt * 16 + (lane >> 2);
#pragma unroll
        for (int nt = 0; nt < 8; nt++) {
            int col = warp_n * 64 + nt * 8 + (lane & 3) * 2;
            float2* p0 = (float2*)(op + (size_t)r0 * DN + col);
            float2* p1 = (float2*)(op + (size_t)(r0 + 8) * DN + col);
            *p0 = make_float2(acc[mt][nt][0], acc[mt][nt][1]);
            *p1 = make_float2(acc[mt][nt][2], acc[mt][nt][3]);
        }
    }
}

// ------------------------------ launch -------------------------------------
extern "C" void kernel_launch(void* const* d_in, const int* in_sizes, int n_in,
                              void* d_out, int out_size) {
    (void)in_sizes; (void)n_in; (void)out_size;
    const float* x       = (const float*)d_in[0];
    const float* signs   = (const float*)d_in[1];
    const float* ps      = (const float*)d_in[2];
    const float* routing = (const float*)d_in[3];
    float* out = (float*)d_out;

    cudaFuncSetAttribute(gemm_kernel, cudaFuncAttributeMaxDynamicSharedMemorySize,
                         SMEM_TOTAL);

    blend_kernel<<<NGROUPS / 256, 256>>>(ps, routing);
    weight_kernel<<<(int)(((size_t)DN * DK / 8) / 256), 256>>>(signs);
    xconv_kernel<<<(int)(((size_t)DM * DK / 8) / 256), 256>>>(x);
    gemm_kernel<<<(DM / BM) * (DN / BN), 128, SMEM_TOTAL>>>(out);
}

// round 9
// speedup vs baseline: 1.2492x; 1.1880x over previous
#include <cuda_runtime.h>
#include <cuda_fp16.h>
#include <cstdint>

// ---------------------------------------------------------------------------
// RoutedBitLinear: out[M,N] = x[M,K] @ (signs * blended_scales)[N,K]^T
// M=8192, N=4096, K=4096, group_size=128, P=8.
// mma.sync.m16n8k16 f16 path (tcgen05 unavailable: harness PTX target sm_103).
// R9 = R5 body (CTA 128x128, 4 warps, warp tile 64x64, BK=32, 4 stages,
// 2 CTAs/SM) + persistent CTAs: grid=296 (all resident), each CTA walks
// tiles t, t+296, ... with a continuous cp.async stream across tile
// boundaries (last 3 iters of tile t prefetch chunks 0..2 of the next tile),
// so epilogue overlaps next tile's prologue; no wave transitions, no
// per-tile pipeline drains. Iteration body is byte-identical to R5.
// ---------------------------------------------------------------------------

#define DM 8192
#define DN 4096
#define DK 4096
#define NGROUPS (DN * DK / 128)   // 131072

#define BM 128
#define BN 128
#define BK 32                      // halves per k-chunk
#define STAGES 4
#define NITER (DK / BK)            // 128
#define TILE_A_BYTES (BM * BK * 2) // 8192
#define STAGE_BYTES (2 * TILE_A_BYTES)      // 16384 (A + B)
#define SMEM_TOTAL (STAGES * STAGE_BYTES)   // 65536 -> 2 CTAs/SM
#define NTILES ((DM / BM) * (DN / BN))      // 2048
#define GRID_P 296                           // 2 x 148 SMs, all resident

// Scratch (static device globals: allocation-free per harness rules)
__device__ __align__(256) __half g_Wh[(size_t)DN * DK];   // 32 MB
__device__ __align__(256) __half g_Xh[(size_t)DM * DK];   // 64 MB
__device__ float g_blend[NGROUPS];

// ------------------------------ helpers ------------------------------------
__device__ __forceinline__ uint32_t smem_u32(const void* p) {
    return (uint32_t)__cvta_generic_to_shared(p);
}
__device__ __forceinline__ void cp_async16(uint32_t dst, const void* src) {
    asm volatile("cp.async.cg.shared.global [%0], [%1], 16;" :: "r"(dst), "l"(src));
}
__device__ __forceinline__ void cp_commit() {
    asm volatile("cp.async.commit_group;");
}
template <int Npend>
__device__ __forceinline__ void cp_wait() {
    asm volatile("cp.async.wait_group %0;" :: "n"(Npend));
}
__device__ __forceinline__ void ldmx4(uint32_t* d, uint32_t addr) {
    asm volatile("ldmatrix.sync.aligned.m8n8.x4.shared.b16 {%0,%1,%2,%3}, [%4];"
                 : "=r"(d[0]), "=r"(d[1]), "=r"(d[2]), "=r"(d[3]) : "r"(addr));
}
__device__ __forceinline__ void mma16816(float* c, const uint32_t* a, const uint32_t* b) {
    asm volatile(
        "mma.sync.aligned.m16n8k16.row.col.f32.f16.f16.f32 "
        "{%0,%1,%2,%3}, {%4,%5,%6,%7}, {%8,%9}, {%0,%1,%2,%3};"
        : "+f"(c[0]), "+f"(c[1]), "+f"(c[2]), "+f"(c[3])
        : "r"(a[0]), "r"(a[1]), "r"(a[2]), "r"(a[3]), "r"(b[0]), "r"(b[1]));
}

// ------------------------------ prep kernels -------------------------------
__global__ void blend_kernel(const float* __restrict__ ps, const float* __restrict__ rt) {
    int g = blockIdx.x * 256 + threadIdx.x;
    float acc = 0.f;
#pragma unroll
    for (int p = 0; p < 8; p++)
        acc = fmaf(rt[p], ps[(size_t)p * NGROUPS + g], acc);
    g_blend[g] = acc;
}

__global__ void weight_kernel(const float* __restrict__ signs) {
    size_t base = ((size_t)blockIdx.x * 256 + threadIdx.x) * 8;
    float s = g_blend[base >> 7];  // flat index >> 7 == o*32 + i/128
    float4 a = *(const float4*)(signs + base);
    float4 b = *(const float4*)(signs + base + 4);
    union { __half2 h[4]; uint4 u; } pk;
    pk.h[0] = __floats2half2_rn(a.x * s, a.y * s);
    pk.h[1] = __floats2half2_rn(a.z * s, a.w * s);
    pk.h[2] = __floats2half2_rn(b.x * s, b.y * s);
    pk.h[3] = __floats2half2_rn(b.z * s, b.w * s);
    *(uint4*)(g_Wh + base) = pk.u;
}

__global__ void xconv_kernel(const float* __restrict__ x) {
    size_t base = ((size_t)blockIdx.x * 256 + threadIdx.x) * 8;
    float4 a = *(const float4*)(x + base);
    float4 b = *(const float4*)(x + base + 4);
    union { __half2 h[4]; uint4 u; } pk;
    pk.h[0] = __floats2half2_rn(a.x, a.y);
    pk.h[1] = __floats2half2_rn(a.z, a.w);
    pk.h[2] = __floats2half2_rn(b.x, b.y);
    pk.h[3] = __floats2half2_rn(b.z, b.w);
    *(uint4*)(g_Xh + base) = pk.u;
}

// ------------------------------ GEMM kernel --------------------------------
// smem per stage: A[128 rows][32 halves] then B[128 rows][32 halves], 64B rows
// XOR-swizzled in 16B chunks: c ^= (row>>1)&3. Conflict-free for cp.async
// writes and all ldmatrix phases.
__global__ void __launch_bounds__(128, 2) gemm_kernel(float* __restrict__ out) {
    extern __shared__ char smem_raw[];
    const uint32_t sbase = smem_u32(smem_raw);
    const int tid = threadIdx.x;
    const int wid = tid >> 5;
    const int lane = tid & 31;
    const int warp_m = wid & 1;    // 2 warps along M (64 rows each)
    const int warp_n = wid >> 1;   // 2 warps along N (64 cols each)

    // tile raster for L2 reuse (GROUP_M=16 over 32 n-tiles, 512 tiles/group)
    auto tile_ptrs = [&](int t, const __half*& pA, const __half*& pB, float*& pO) {
        int group = t >> 9;
        int rem = t & 511;
        int mt_blk = group * 16 + (rem & 15);
        int nt_blk = rem >> 4;
        size_t m0 = (size_t)mt_blk * BM;
        size_t n0 = (size_t)nt_blk * BN;
        pA = g_Xh + m0 * DK;
        pB = g_Wh + n0 * DK;
        pO = out + m0 * DN + n0;
    };

    auto load_stage = [&](int s, const __half* pA, const __half* pB, int kc) {
        uint32_t base = sbase + s * STAGE_BYTES;
        int k0 = kc * BK;
#pragma unroll
        for (int j = 0; j < 4; j++) {          // A then B: 128 rows x 4 chunks each
            int i = tid + j * 128;             // 0..511
            int row = i >> 2;
            int c = i & 3;
            uint32_t off = (uint32_t)(row * 64 + ((c ^ ((row >> 1) & 3)) * 16));
            cp_async16(base + off, pA + (size_t)row * DK + k0 + c * 8);
            cp_async16(base + TILE_A_BYTES + off, pB + (size_t)row * DK + k0 + c * 8);
        }
    };

    // per-thread ldmatrix address components (xor term constant across mt/h
    // tiles: tile strides are 16 rows, and (16>>1)&3 == 0)
    const int rowA = warp_m * 64 + (lane & 15);
    const int xa = (rowA >> 1) & 3;
    const uint32_t offA = (uint32_t)(rowA * 64);
    const int rowB = warp_n * 64 + ((lane >> 4) << 3) + (lane & 7);
    const int xb = (rowB >> 1) & 3;
    const uint32_t offB = (uint32_t)(rowB * 64);

    float acc[4][8][4];
#pragma unroll
    for (int mt = 0; mt < 4; mt++)
#pragma unroll
        for (int nt = 0; nt < 8; nt++)
#pragma unroll
            for (int r = 0; r < 4; r++) acc[mt][nt][r] = 0.f;

    int t = blockIdx.x;
    const __half *pA, *pB;
    float* pO;
    tile_ptrs(t, pA, pB, pO);

    // prologue: chunks 0..2 of first tile
#pragma unroll
    for (int s = 0; s < STAGES - 1; s++) { load_stage(s, pA, pB, s); cp_commit(); }

    while (true) {
        const int t_next = t + GRID_P;
        const bool have_next = (t_next < NTILES);
        const __half *pAn = pA, *pBn = pB;
        float* pOn = pO;
        if (have_next) tile_ptrs(t_next, pAn, pBn, pOn);

        for (int it = 0; it < NITER; it++) {
            cp_wait<STAGES - 2>();
            __syncthreads();

            // continuous load stream: tail iterations prefetch next tile
            int kc = it + STAGES - 1;
            if (kc < NITER) load_stage(kc & (STAGES - 1), pA, pB, kc);
            else if (have_next) load_stage(kc & (STAGES - 1), pAn, pBn, kc - NITER);
            cp_commit();

            const uint32_t stA = sbase + (it & (STAGES - 1)) * STAGE_BYTES;
            const uint32_t stB = stA + TILE_A_BYTES;
#pragma unroll
            for (int s16 = 0; s16 < 2; s16++) {
                uint32_t a[4][4];
                uint32_t b[8][2];
                const int cA = (s16 * 2 + (lane >> 4)) ^ xa;
#pragma unroll
                for (int mt = 0; mt < 4; mt++)
                    ldmx4(a[mt], stA + offA + mt * 1024 + cA * 16);
                const int cB = (s16 * 2 + ((lane >> 3) & 1)) ^ xb;
#pragma unroll
                for (int h = 0; h < 4; h++) {  // 4 x (16 rows of B) = 64 cols
                    uint32_t r[4];
                    ldmx4(r, stB + offB + h * 1024 + cB * 16);
                    b[h * 2 + 0][0] = r[0]; b[h * 2 + 0][1] = r[1];
                    b[h * 2 + 1][0] = r[2]; b[h * 2 + 1][1] = r[3];
                }
#pragma unroll
                for (int mt = 0; mt < 4; mt++)
#pragma unroll
                    for (int nt = 0; nt < 8; nt++)
                        mma16816(acc[mt][nt], a[mt], b[nt]);
            }
        }

        // epilogue for tile t (registers only; overlaps next tile's pipeline)
#pragma unroll
        for (int mt = 0; mt < 4; mt++) {
            int r0 = warp_m * 64 + mt * 16 + (lane >> 2);
#pragma unroll
            for (int nt = 0; nt < 8; nt++) {
                int col = warp_n * 64 + nt * 8 + (lane & 3) * 2;
                float2* p0 = (float2*)(pO + (size_t)r0 * DN + col);
                float2* p1 = (float2*)(pO + (size_t)(r0 + 8) * DN + col);
                *p0 = make_float2(acc[mt][nt][0], acc[mt][nt][1]);
                *p1 = make_float2(acc[mt][nt][2], acc[mt][nt][3]);
                acc[mt][nt][0] = 0.f; acc[mt][nt][1] = 0.f;
                acc[mt][nt][2] = 0.f; acc[mt][nt][3] = 0.f;
            }
        }

        if (!have_next) break;
        t = t_next; pA = pAn; pB = pBn; pO = pOn;
    }
}

// ------------------------------ launch -------------------------------------
extern "C" void kernel_launch(void* const* d_in, const int* in_sizes, int n_in,
                              void* d_out, int out_size) {
    (void)in_sizes; (void)n_in; (void)out_size;
    const float* x       = (const float*)d_in[0];
    const float* signs   = (const float*)d_in[1];
    const float* ps      = (const float*)d_in[2];
    const float* routing = (const float*)d_in[3];
    float* out = (float*)d_out;

    cudaFuncSetAttribute(gemm_kernel, cudaFuncAttributeMaxDynamicSharedMemorySize,
                         SMEM_TOTAL);

    blend_kernel<<<NGROUPS / 256, 256>>>(ps, routing);
    weight_kernel<<<(int)(((size_t)DN * DK / 8) / 256), 256>>>(signs);
    xconv_kernel<<<(int)(((size_t)DM * DK / 8) / 256), 256>>>(x);
    gemm_kernel<<<GRID_P, 128, SMEM_TOTAL>>>(out);
}

// round 14
// speedup vs baseline: 1.2741x; 1.0199x over previous
#include <cuda_runtime.h>
#include <cuda_fp16.h>
#include <cstdint>

// ---------------------------------------------------------------------------
// RoutedBitLinear: out[M,N] = x[M,K] @ (signs * blended_scales)[N,K]^T
// M=8192, N=4096, K=4096, group_size=128, P=8.
// mma.sync.m16n8k16 f16 path (tcgen05 unavailable: harness PTX target sm_103).
// R10 = R9 (persistent grid=296, R5 body: CTA 128x128, 4 warps, warp tile
// 64x64, BK=32, 2 CTAs/SM, continuous cross-tile load stream) + STAGES 4->6:
// prefetch distance 160 k-elems absorbs L2/L1tex latency jitter so the
// cp.async wait almost never blocks. 6 is not a power of 2 and 128%6!=0, so
// stage indices are explicit wrap counters continuous across tiles.
// Iteration body untouched (R6/R8 lesson: don't fight ptxas's schedule).
// ---------------------------------------------------------------------------

#define DM 8192
#define DN 4096
#define DK 4096
#define NGROUPS (DN * DK / 128)   // 131072

#define BM 128
#define BN 128
#define BK 32                      // halves per k-chunk
#define STAGES 6
#define NITER (DK / BK)            // 128
#define TILE_A_BYTES (BM * BK * 2) // 8192
#define STAGE_BYTES (2 * TILE_A_BYTES)      // 16384 (A + B)
#define SMEM_TOTAL (STAGES * STAGE_BYTES)   // 98304 -> 2 CTAs/SM (192KB)
#define NTILES ((DM / BM) * (DN / BN))      // 2048
#define GRID_P 296                           // 2 x 148 SMs, all resident

// Scratch (static device globals: allocation-free per harness rules)
__device__ __align__(256) __half g_Wh[(size_t)DN * DK];   // 32 MB
__device__ __align__(256) __half g_Xh[(size_t)DM * DK];   // 64 MB
__device__ float g_blend[NGROUPS];

// ------------------------------ helpers ------------------------------------
__device__ __forceinline__ uint32_t smem_u32(const void* p) {
    return (uint32_t)__cvta_generic_to_shared(p);
}
__device__ __forceinline__ void cp_async16(uint32_t dst, const void* src) {
    asm volatile("cp.async.cg.shared.global [%0], [%1], 16;" :: "r"(dst), "l"(src));
}
__device__ __forceinline__ void cp_commit() {
    asm volatile("cp.async.commit_group;");
}
template <int Npend>
__device__ __forceinline__ void cp_wait() {
    asm volatile("cp.async.wait_group %0;" :: "n"(Npend));
}
__device__ __forceinline__ void ldmx4(uint32_t* d, uint32_t addr) {
    asm volatile("ldmatrix.sync.aligned.m8n8.x4.shared.b16 {%0,%1,%2,%3}, [%4];"
                 : "=r"(d[0]), "=r"(d[1]), "=r"(d[2]), "=r"(d[3]) : "r"(addr));
}
__device__ __forceinline__ void mma16816(float* c, const uint32_t* a, const uint32_t* b) {
    asm volatile(
        "mma.sync.aligned.m16n8k16.row.col.f32.f16.f16.f32 "
        "{%0,%1,%2,%3}, {%4,%5,%6,%7}, {%8,%9}, {%0,%1,%2,%3};"
        : "+f"(c[0]), "+f"(c[1]), "+f"(c[2]), "+f"(c[3])
        : "r"(a[0]), "r"(a[1]), "r"(a[2]), "r"(a[3]), "r"(b[0]), "r"(b[1]));
}

// ------------------------------ prep kernels -------------------------------
__global__ void blend_kernel(const float* __restrict__ ps, const float* __restrict__ rt) {
    int g = blockIdx.x * 256 + threadIdx.x;
    float acc = 0.f;
#pragma unroll
    for (int p = 0; p < 8; p++)
        acc = fmaf(rt[p], ps[(size_t)p * NGROUPS + g], acc);
    g_blend[g] = acc;
}

__global__ void weight_kernel(const float* __restrict__ signs) {
    size_t base = ((size_t)blockIdx.x * 256 + threadIdx.x) * 8;
    float s = g_blend[base >> 7];  // flat index >> 7 == o*32 + i/128
    float4 a = *(const float4*)(signs + base);
    float4 b = *(const float4*)(signs + base + 4);
    union { __half2 h[4]; uint4 u; } pk;
    pk.h[0] = __floats2half2_rn(a.x * s, a.y * s);
    pk.h[1] = __floats2half2_rn(a.z * s, a.w * s);
    pk.h[2] = __floats2half2_rn(b.x * s, b.y * s);
    pk.h[3] = __floats2half2_rn(b.z * s, b.w * s);
    *(uint4*)(g_Wh + base) = pk.u;
}

__global__ void xconv_kernel(const float* __restrict__ x) {
    size_t base = ((size_t)blockIdx.x * 256 + threadIdx.x) * 8;
    float4 a = *(const float4*)(x + base);
    float4 b = *(const float4*)(x + base + 4);
    union { __half2 h[4]; uint4 u; } pk;
    pk.h[0] = __floats2half2_rn(a.x, a.y);
    pk.h[1] = __floats2half2_rn(a.z, a.w);
    pk.h[2] = __floats2half2_rn(b.x, b.y);
    pk.h[3] = __floats2half2_rn(b.z, b.w);
    *(uint4*)(g_Xh + base) = pk.u;
}

// ------------------------------ GEMM kernel --------------------------------
// smem per stage: A[128 rows][32 halves] then B[128 rows][32 halves], 64B rows
// XOR-swizzled in 16B chunks: c ^= (row>>1)&3. Conflict-free for cp.async
// writes and all ldmatrix phases.
__global__ void __launch_bounds__(128, 2) gemm_kernel(float* __restrict__ out) {
    extern __shared__ char smem_raw[];
    const uint32_t sbase = smem_u32(smem_raw);
    const int tid = threadIdx.x;
    const int wid = tid >> 5;
    const int lane = tid & 31;
    const int warp_m = wid & 1;    // 2 warps along M (64 rows each)
    const int warp_n = wid >> 1;   // 2 warps along N (64 cols each)

    // tile raster for L2 reuse (GROUP_M=16 over 32 n-tiles, 512 tiles/group)
    auto tile_ptrs = [&](int t, const __half*& pA, const __half*& pB, float*& pO) {
        int group = t >> 9;
        int rem = t & 511;
        int mt_blk = group * 16 + (rem & 15);
        int nt_blk = rem >> 4;
        size_t m0 = (size_t)mt_blk * BM;
        size_t n0 = (size_t)nt_blk * BN;
        pA = g_Xh + m0 * DK;
        pB = g_Wh + n0 * DK;
        pO = out + m0 * DN + n0;
    };

    auto load_stage = [&](int s, const __half* pA, const __half* pB, int kc) {
        uint32_t base = sbase + s * STAGE_BYTES;
        int k0 = kc * BK;
#pragma unroll
        for (int j = 0; j < 4; j++) {          // A then B: 128 rows x 4 chunks each
            int i = tid + j * 128;             // 0..511
            int row = i >> 2;
            int c = i & 3;
            uint32_t off = (uint32_t)(row * 64 + ((c ^ ((row >> 1) & 3)) * 16));
            cp_async16(base + off, pA + (size_t)row * DK + k0 + c * 8);
            cp_async16(base + TILE_A_BYTES + off, pB + (size_t)row * DK + k0 + c * 8);
        }
    };

    // per-thread ldmatrix address components (xor term constant across mt/h
    // tiles: tile strides are 16 rows, and (16>>1)&3 == 0)
    const int rowA = warp_m * 64 + (lane & 15);
    const int xa = (rowA >> 1) & 3;
    const uint32_t offA = (uint32_t)(rowA * 64);
    const int rowB = warp_n * 64 + ((lane >> 4) << 3) + (lane & 7);
    const int xb = (rowB >> 1) & 3;
    const uint32_t offB = (uint32_t)(rowB * 64);

    float acc[4][8][4];
#pragma unroll
    for (int mt = 0; mt < 4; mt++)
#pragma unroll
        for (int nt = 0; nt < 8; nt++)
#pragma unroll
            for (int r = 0; r < 4; r++) acc[mt][nt][r] = 0.f;

    int t = blockIdx.x;
    const __half *pA, *pB;
    float* pO;
    tile_ptrs(t, pA, pB, pO);

    // stage wrap counters, continuous across tiles (128 % 6 != 0)
    int sl = 0;  // stage for the next load
    int sc = 0;  // stage to consume this iteration

    // prologue: chunks 0..STAGES-2 of first tile
#pragma unroll
    for (int s = 0; s < STAGES - 1; s++) {
        load_stage(sl, pA, pB, s);
        cp_commit();
        sl = (sl + 1 == STAGES) ? 0 : sl + 1;
    }

    while (true) {
        const int t_next = t + GRID_P;
        const bool have_next = (t_next < NTILES);
        const __half *pAn = pA, *pBn = pB;
        float* pOn = pO;
        if (have_next) tile_ptrs(t_next, pAn, pBn, pOn);

        for (int it = 0; it < NITER; it++) {
            cp_wait<STAGES - 2>();
            __syncthreads();

            // continuous load stream: tail iterations prefetch next tile
            int kc = it + STAGES - 1;
            if (kc < NITER) load_stage(sl, pA, pB, kc);
            else if (have_next) load_stage(sl, pAn, pBn, kc - NITER);
            cp_commit();
            sl = (sl + 1 == STAGES) ? 0 : sl + 1;

            const uint32_t stA = sbase + sc * STAGE_BYTES;
            const uint32_t stB = stA + TILE_A_BYTES;
            sc = (sc + 1 == STAGES) ? 0 : sc + 1;
#pragma unroll
            for (int s16 = 0; s16 < 2; s16++) {
                uint32_t a[4][4];
                uint32_t b[8][2];
                const int cA = (s16 * 2 + (lane >> 4)) ^ xa;
#pragma unroll
                for (int mt = 0; mt < 4; mt++)
                    ldmx4(a[mt], stA + offA + mt * 1024 + cA * 16);
                const int cB = (s16 * 2 + ((lane >> 3) & 1)) ^ xb;
#pragma unroll
                for (int h = 0; h < 4; h++) {  // 4 x (16 rows of B) = 64 cols
                    uint32_t r[4];
                    ldmx4(r, stB + offB + h * 1024 + cB * 16);
                    b[h * 2 + 0][0] = r[0]; b[h * 2 + 0][1] = r[1];
                    b[h * 2 + 1][0] = r[2]; b[h * 2 + 1][1] = r[3];
                }
#pragma unroll
                for (int mt = 0; mt < 4; mt++)
#pragma unroll
                    for (int nt = 0; nt < 8; nt++)
                        mma16816(acc[mt][nt], a[mt], b[nt]);
            }
        }

        // epilogue for tile t (registers only; overlaps next tile's pipeline)
#pragma unroll
        for (int mt = 0; mt < 4; mt++) {
            int r0 = warp_m * 64 + mt * 16 + (lane >> 2);
#pragma unroll
            for (int nt = 0; nt < 8; nt++) {
                int col = warp_n * 64 + nt * 8 + (lane & 3) * 2;
                float2* p0 = (float2*)(pO + (size_t)r0 * DN + col);
                float2* p1 = (float2*)(pO + (size_t)(r0 + 8) * DN + col);
                *p0 = make_float2(acc[mt][nt][0], acc[mt][nt][1]);
                *p1 = make_float2(acc[mt][nt][2], acc[mt][nt][3]);
                acc[mt][nt][0] = 0.f; acc[mt][nt][1] = 0.f;
                acc[mt][nt][2] = 0.f; acc[mt][nt][3] = 0.f;
            }
        }

        if (!have_next) break;
        t = t_next; pA = pAn; pB = pBn; pO = pOn;
    }
}

// ------------------------------ launch -------------------------------------
extern "C" void kernel_launch(void* const* d_in, const int* in_sizes, int n_in,
                              void* d_out, int out_size) {
    (void)in_sizes; (void)n_in; (void)out_size;
    const float* x       = (const float*)d_in[0];
    const float* signs   = (const float*)d_in[1];
    const float* ps      = (const float*)d_in[2];
    const float* routing = (const float*)d_in[3];
    float* out = (float*)d_out;

    cudaFuncSetAttribute(gemm_kernel, cudaFuncAttributeMaxDynamicSharedMemorySize,
                         SMEM_TOTAL);

    blend_kernel<<<NGROUPS / 256, 256>>>(ps, routing);
    weight_kernel<<<(int)(((size_t)DN * DK / 8) / 256), 256>>>(signs);
    xconv_kernel<<<(int)(((size_t)DM * DK / 8) / 256), 256>>>(x);
    gemm_kernel<<<GRID_P, 128, SMEM_TOTAL>>>(out);
}

// round 16
// speedup vs baseline: 1.2748x; 1.0006x over previous
#include <cuda_runtime.h>
#include <cuda_fp16.h>
#include <cstdint>

// ---------------------------------------------------------------------------
// RoutedBitLinear: out[M,N] = x[M,K] @ (signs * blended_scales)[N,K]^T
// M=8192, N=4096, K=4096, group_size=128, P=8.
// mma.sync.m16n8k16 f16 path (tcgen05 unavailable: harness PTX target sm_103).
// R15 = R10 (persistent grid=296, R5 body, continuous cross-tile stream)
//  + STAGES 6->7 (112KB/CTA, still 2 CTAs/SM: 2x113KB <= 228KB)
//  + blend fused into weight_kernel (one less launch, no g_blend round-trip)
//  + __ldcs on streaming prep reads, __stcs on the 128MB output epilogue
//    (write-once lines evict first; don't displace A/B operand tiles in L2).
// Mainloop body untouched (R6/R8 lesson).
// ---------------------------------------------------------------------------

#define DM 8192
#define DN 4096
#define DK 4096
#define NGROUPS (DN * DK / 128)   // 131072

#define BM 128
#define BN 128
#define BK 32                      // halves per k-chunk
#define STAGES 7
#define NITER (DK / BK)            // 128
#define TILE_A_BYTES (BM * BK * 2) // 8192
#define STAGE_BYTES (2 * TILE_A_BYTES)      // 16384 (A + B)
#define SMEM_TOTAL (STAGES * STAGE_BYTES)   // 114688 -> 2 CTAs/SM
#define NTILES ((DM / BM) * (DN / BN))      // 2048
#define GRID_P 296                           // 2 x 148 SMs, all resident

// Scratch (static device globals: allocation-free per harness rules)
__device__ __align__(256) __half g_Wh[(size_t)DN * DK];   // 32 MB
__device__ __align__(256) __half g_Xh[(size_t)DM * DK];   // 64 MB

// ------------------------------ helpers ------------------------------------
__device__ __forceinline__ uint32_t smem_u32(const void* p) {
    return (uint32_t)__cvta_generic_to_shared(p);
}
__device__ __forceinline__ void cp_async16(uint32_t dst, const void* src) {
    asm volatile("cp.async.cg.shared.global [%0], [%1], 16;" :: "r"(dst), "l"(src));
}
__device__ __forceinline__ void cp_commit() {
    asm volatile("cp.async.commit_group;");
}
template <int Npend>
__device__ __forceinline__ void cp_wait() {
    asm volatile("cp.async.wait_group %0;" :: "n"(Npend));
}
__device__ __forceinline__ void ldmx4(uint32_t* d, uint32_t addr) {
    asm volatile("ldmatrix.sync.aligned.m8n8.x4.shared.b16 {%0,%1,%2,%3}, [%4];"
                 : "=r"(d[0]), "=r"(d[1]), "=r"(d[2]), "=r"(d[3]) : "r"(addr));
}
__device__ __forceinline__ void mma16816(float* c, const uint32_t* a, const uint32_t* b) {
    asm volatile(
        "mma.sync.aligned.m16n8k16.row.col.f32.f16.f16.f32 "
        "{%0,%1,%2,%3}, {%4,%5,%6,%7}, {%8,%9}, {%0,%1,%2,%3};"
        : "+f"(c[0]), "+f"(c[1]), "+f"(c[2]), "+f"(c[3])
        : "r"(a[0]), "r"(a[1]), "r"(a[2]), "r"(a[3]), "r"(b[0]), "r"(b[1]));
}

// ------------------------------ prep kernels -------------------------------
// weight_kernel: blend fused. Each block covers 2048 contiguous weight elems
// = 16 scale groups (2048/128). 16 threads compute the blended scales into
// smem, then all 256 threads build fp16 weights.
__global__ void weight_kernel(const float* __restrict__ signs,
                              const float* __restrict__ ps,
                              const float* __restrict__ rt) {
    __shared__ float sblend[16];
    if (threadIdx.x < 16) {
        int g = blockIdx.x * 16 + threadIdx.x;
        float acc = 0.f;
#pragma unroll
        for (int p = 0; p < 8; p++)
            acc = fmaf(__ldg(rt + p), __ldg(ps + (size_t)p * NGROUPS + g), acc);
        sblend[threadIdx.x] = acc;
    }
    __syncthreads();
    size_t base = ((size_t)blockIdx.x * 256 + threadIdx.x) * 8;
    float s = sblend[threadIdx.x >> 4];   // (threadIdx.x*8)/128
    float4 a = __ldcs((const float4*)(signs + base));
    float4 b = __ldcs((const float4*)(signs + base + 4));
    union { __half2 h[4]; uint4 u; } pk;
    pk.h[0] = __floats2half2_rn(a.x * s, a.y * s);
    pk.h[1] = __floats2half2_rn(a.z * s, a.w * s);
    pk.h[2] = __floats2half2_rn(b.x * s, b.y * s);
    pk.h[3] = __floats2half2_rn(b.z * s, b.w * s);
    *(uint4*)(g_Wh + base) = pk.u;
}

__global__ void xconv_kernel(const float* __restrict__ x) {
    size_t base = ((size_t)blockIdx.x * 256 + threadIdx.x) * 8;
    float4 a = __ldcs((const float4*)(x + base));
    float4 b = __ldcs((const float4*)(x + base + 4));
    union { __half2 h[4]; uint4 u; } pk;
    pk.h[0] = __floats2half2_rn(a.x, a.y);
    pk.h[1] = __floats2half2_rn(a.z, a.w);
    pk.h[2] = __floats2half2_rn(b.x, b.y);
    pk.h[3] = __floats2half2_rn(b.z, b.w);
    *(uint4*)(g_Xh + base) = pk.u;
}

// ------------------------------ GEMM kernel --------------------------------
// smem per stage: A[128 rows][32 halves] then B[128 rows][32 halves], 64B rows
// XOR-swizzled in 16B chunks: c ^= (row>>1)&3. Conflict-free for cp.async
// writes and all ldmatrix phases.
__global__ void __launch_bounds__(128, 2) gemm_kernel(float* __restrict__ out) {
    extern __shared__ char smem_raw[];
    const uint32_t sbase = smem_u32(smem_raw);
    const int tid = threadIdx.x;
    const int wid = tid >> 5;
    const int lane = tid & 31;
    const int warp_m = wid & 1;    // 2 warps along M (64 rows each)
    const int warp_n = wid >> 1;   // 2 warps along N (64 cols each)

    // tile raster for L2 reuse (GROUP_M=16 over 32 n-tiles, 512 tiles/group)
    auto tile_ptrs = [&](int t, const __half*& pA, const __half*& pB, float*& pO) {
        int group = t >> 9;
        int rem = t & 511;
        int mt_blk = group * 16 + (rem & 15);
        int nt_blk = rem >> 4;
        size_t m0 = (size_t)mt_blk * BM;
        size_t n0 = (size_t)nt_blk * BN;
        pA = g_Xh + m0 * DK;
        pB = g_Wh + n0 * DK;
        pO = out + m0 * DN + n0;
    };

    auto load_stage = [&](int s, const __half* pA, const __half* pB, int kc) {
        uint32_t base = sbase + s * STAGE_BYTES;
        int k0 = kc * BK;
#pragma unroll
        for (int j = 0; j < 4; j++) {          // A then B: 128 rows x 4 chunks each
            int i = tid + j * 128;             // 0..511
            int row = i >> 2;
            int c = i & 3;
            uint32_t off = (uint32_t)(row * 64 + ((c ^ ((row >> 1) & 3)) * 16));
            cp_async16(base + off, pA + (size_t)row * DK + k0 + c * 8);
            cp_async16(base + TILE_A_BYTES + off, pB + (size_t)row * DK + k0 + c * 8);
        }
    };

    // per-thread ldmatrix address components (xor term constant across mt/h
    // tiles: tile strides are 16 rows, and (16>>1)&3 == 0)
    const int rowA = warp_m * 64 + (lane & 15);
    const int xa = (rowA >> 1) & 3;
    const uint32_t offA = (uint32_t)(rowA * 64);
    const int rowB = warp_n * 64 + ((lane >> 4) << 3) + (lane & 7);
    const int xb = (rowB >> 1) & 3;
    const uint32_t offB = (uint32_t)(rowB * 64);

    float acc[4][8][4];
#pragma unroll
    for (int mt = 0; mt < 4; mt++)
#pragma unroll
        for (int nt = 0; nt < 8; nt++)
#pragma unroll
            for (int r = 0; r < 4; r++) acc[mt][nt][r] = 0.f;

    int t = blockIdx.x;
    const __half *pA, *pB;
    float* pO;
    tile_ptrs(t, pA, pB, pO);

    // stage wrap counters, continuous across tiles (128 % 7 != 0)
    int sl = 0;  // stage for the next load
    int sc = 0;  // stage to consume this iteration

    // prologue: chunks 0..STAGES-2 of first tile
#pragma unroll
    for (int s = 0; s < STAGES - 1; s++) {
        load_stage(sl, pA, pB, s);
        cp_commit();
        sl = (sl + 1 == STAGES) ? 0 : sl + 1;
    }

    while (true) {
        const int t_next = t + GRID_P;
        const bool have_next = (t_next < NTILES);
        const __half *pAn = pA, *pBn = pB;
        float* pOn = pO;
        if (have_next) tile_ptrs(t_next, pAn, pBn, pOn);

        for (int it = 0; it < NITER; it++) {
            cp_wait<STAGES - 2>();
            __syncthreads();

            // continuous load stream: tail iterations prefetch next tile
            int kc = it + STAGES - 1;
            if (kc < NITER) load_stage(sl, pA, pB, kc);
            else if (have_next) load_stage(sl, pAn, pBn, kc - NITER);
            cp_commit();
            sl = (sl + 1 == STAGES) ? 0 : sl + 1;

            const uint32_t stA = sbase + sc * STAGE_BYTES;
            const uint32_t stB = stA + TILE_A_BYTES;
            sc = (sc + 1 == STAGES) ? 0 : sc + 1;
#pragma unroll
            for (int s16 = 0; s16 < 2; s16++) {
                uint32_t a[4][4];
                uint32_t b[8][2];
                const int cA = (s16 * 2 + (lane >> 4)) ^ xa;
#pragma unroll
                for (int mt = 0; mt < 4; mt++)
                    ldmx4(a[mt], stA + offA + mt * 1024 + cA * 16);
                const int cB = (s16 * 2 + ((lane >> 3) & 1)) ^ xb;
#pragma unroll
                for (int h = 0; h < 4; h++) {  // 4 x (16 rows of B) = 64 cols
                    uint32_t r[4];
                    ldmx4(r, stB + offB + h * 1024 + cB * 16);
                    b[h * 2 + 0][0] = r[0]; b[h * 2 + 0][1] = r[1];
                    b[h * 2 + 1][0] = r[2]; b[h * 2 + 1][1] = r[3];
                }
#pragma unroll
                for (int mt = 0; mt < 4; mt++)
#pragma unroll
                    for (int nt = 0; nt < 8; nt++)
                        mma16816(acc[mt][nt], a[mt], b[nt]);
            }
        }

        // epilogue for tile t: streaming stores (write-once; evict-first so
        // out lines don't displace A/B operand tiles in L2). Overlaps next
        // tile's pipeline.
#pragma unroll
        for (int mt = 0; mt < 4; mt++) {
            int r0 = warp_m * 64 + mt * 16 + (lane >> 2);
#pragma unroll
            for (int nt = 0; nt < 8; nt++) {
                int col = warp_n * 64 + nt * 8 + (lane & 3) * 2;
                __stcs((float2*)(pO + (size_t)r0 * DN + col),
                       make_float2(acc[mt][nt][0], acc[mt][nt][1]));
                __stcs((float2*)(pO + (size_t)(r0 + 8) * DN + col),
                       make_float2(acc[mt][nt][2], acc[mt][nt][3]));
                acc[mt][nt][0] = 0.f; acc[mt][nt][1] = 0.f;
                acc[mt][nt][2] = 0.f; acc[mt][nt][3] = 0.f;
            }
        }

        if (!have_next) break;
        t = t_next; pA = pAn; pB = pBn; pO = pOn;
    }
}

// ------------------------------ launch -------------------------------------
extern "C" void kernel_launch(void* const* d_in, const int* in_sizes, int n_in,
                              void* d_out, int out_size) {
    (void)in_sizes; (void)n_in; (void)out_size;
    const float* x       = (const float*)d_in[0];
    const float* signs   = (const float*)d_in[1];
    const float* ps      = (const float*)d_in[2];
    const float* routing = (const float*)d_in[3];
    float* out = (float*)d_out;

    cudaFuncSetAttribute(gemm_kernel, cudaFuncAttributeMaxDynamicSharedMemorySize,
                         SMEM_TOTAL);

    weight_kernel<<<(int)(((size_t)DN * DK / 8) / 256), 256>>>(signs, ps, routing);
    xconv_kernel<<<(int)(((size_t)DM * DK / 8) / 256), 256>>>(x);
    gemm_kernel<<<GRID_P, 128, SMEM_TOTAL>>>(out);
}

// round 17
// speedup vs baseline: 1.2822x; 1.0058x over previous
#include <cuda_runtime.h>
#include <cuda_fp16.h>
#include <cstdint>

// ---------------------------------------------------------------------------
// RoutedBitLinear: out[M,N] = x[M,K] @ (signs * blended_scales)[N,K]^T
// M=8192, N=4096, K=4096, group_size=128, P=8.
// mma.sync.m16n8k16 f16 path (tcgen05 unavailable: harness PTX target sm_103).
// R17 = R15 GEMM (persistent grid=296, R5 body, STAGES=7, continuous
// cross-tile stream, streaming-store epilogue) + fused single prep kernel:
// weight-build and x-convert blocks interleaved 1:2 in one launch, so the
// two BW-bound streams overlap instead of serializing (one launch boundary
// and one ramp/tail removed). GEMM mainloop untouched.
// ---------------------------------------------------------------------------

#define DM 8192
#define DN 4096
#define DK 4096
#define NGROUPS (DN * DK / 128)   // 131072

#define BM 128
#define BN 128
#define BK 32                      // halves per k-chunk
#define STAGES 7
#define NITER (DK / BK)            // 128
#define TILE_A_BYTES (BM * BK * 2) // 8192
#define STAGE_BYTES (2 * TILE_A_BYTES)      // 16384 (A + B)
#define SMEM_TOTAL (STAGES * STAGE_BYTES)   // 114688 -> 2 CTAs/SM
#define NTILES ((DM / BM) * (DN / BN))      // 2048
#define GRID_P 296                           // 2 x 148 SMs, all resident

#define NW_BLOCKS ((int)(((size_t)DN * DK / 8) / 256))   // 8192
#define NX_BLOCKS ((int)(((size_t)DM * DK / 8) / 256))   // 16384
#define PREP_BLOCKS (NW_BLOCKS + NX_BLOCKS)              // 24576

// Scratch (static device globals: allocation-free per harness rules)
__device__ __align__(256) __half g_Wh[(size_t)DN * DK];   // 32 MB
__device__ __align__(256) __half g_Xh[(size_t)DM * DK];   // 64 MB

// ------------------------------ helpers ------------------------------------
__device__ __forceinline__ uint32_t smem_u32(const void* p) {
    return (uint32_t)__cvta_generic_to_shared(p);
}
__device__ __forceinline__ void cp_async16(uint32_t dst, const void* src) {
    asm volatile("cp.async.cg.shared.global [%0], [%1], 16;" :: "r"(dst), "l"(src));
}
__device__ __forceinline__ void cp_commit() {
    asm volatile("cp.async.commit_group;");
}
template <int Npend>
__device__ __forceinline__ void cp_wait() {
    asm volatile("cp.async.wait_group %0;" :: "n"(Npend));
}
__device__ __forceinline__ void ldmx4(uint32_t* d, uint32_t addr) {
    asm volatile("ldmatrix.sync.aligned.m8n8.x4.shared.b16 {%0,%1,%2,%3}, [%4];"
                 : "=r"(d[0]), "=r"(d[1]), "=r"(d[2]), "=r"(d[3]) : "r"(addr));
}
__device__ __forceinline__ void mma16816(float* c, const uint32_t* a, const uint32_t* b) {
    asm volatile(
        "mma.sync.aligned.m16n8k16.row.col.f32.f16.f16.f32 "
        "{%0,%1,%2,%3}, {%4,%5,%6,%7}, {%8,%9}, {%0,%1,%2,%3};"
        : "+f"(c[0]), "+f"(c[1]), "+f"(c[2]), "+f"(c[3])
        : "r"(a[0]), "r"(a[1]), "r"(a[2]), "r"(a[3]), "r"(b[0]), "r"(b[1]));
}

// ------------------------------ fused prep kernel --------------------------
// Blocks interleaved 1:2 (weight : xconv). bid%3==0 -> weight block
// (wbid=bid/3 in [0,8192)); else xconv block (xbid=2*(bid/3)+(bid%3-1) in
// [0,16384)). Both streams are pure BW; interleaving keeps them concurrent.
__global__ void prep_kernel(const float* __restrict__ x,
                            const float* __restrict__ signs,
                            const float* __restrict__ ps,
                            const float* __restrict__ rt) {
    __shared__ float sblend[16];
    const int bid = blockIdx.x;
    const int grp = bid / 3;
    const int rem = bid - grp * 3;

    if (rem == 0) {
        // ---- weight block: 2048 contiguous weight elems = 16 scale groups
        const int wbid = grp;
        if (threadIdx.x < 16) {
            int g = wbid * 16 + threadIdx.x;
            float acc = 0.f;
#pragma unroll
            for (int p = 0; p < 8; p++)
                acc = fmaf(__ldg(rt + p), __ldg(ps + (size_t)p * NGROUPS + g), acc);
            sblend[threadIdx.x] = acc;
        }
        __syncthreads();
        size_t base = ((size_t)wbid * 256 + threadIdx.x) * 8;
        float s = sblend[threadIdx.x >> 4];   // (threadIdx.x*8)/128
        float4 a = __ldcs((const float4*)(signs + base));
        float4 b = __ldcs((const float4*)(signs + base + 4));
        union { __half2 h[4]; uint4 u; } pk;
        pk.h[0] = __floats2half2_rn(a.x * s, a.y * s);
        pk.h[1] = __floats2half2_rn(a.z * s, a.w * s);
        pk.h[2] = __floats2half2_rn(b.x * s, b.y * s);
        pk.h[3] = __floats2half2_rn(b.z * s, b.w * s);
        *(uint4*)(g_Wh + base) = pk.u;
    } else {
        // ---- xconv block
        const int xbid = 2 * grp + (rem - 1);
        size_t base = ((size_t)xbid * 256 + threadIdx.x) * 8;
        float4 a = __ldcs((const float4*)(x + base));
        float4 b = __ldcs((const float4*)(x + base + 4));
        union { __half2 h[4]; uint4 u; } pk;
        pk.h[0] = __floats2half2_rn(a.x, a.y);
        pk.h[1] = __floats2half2_rn(a.z, a.w);
        pk.h[2] = __floats2half2_rn(b.x, b.y);
        pk.h[3] = __floats2half2_rn(b.z, b.w);
        *(uint4*)(g_Xh + base) = pk.u;
    }
}

// ------------------------------ GEMM kernel --------------------------------
// smem per stage: A[128 rows][32 halves] then B[128 rows][32 halves], 64B rows
// XOR-swizzled in 16B chunks: c ^= (row>>1)&3. Conflict-free for cp.async
// writes and all ldmatrix phases.
__global__ void __launch_bounds__(128, 2) gemm_kernel(float* __restrict__ out) {
    extern __shared__ char smem_raw[];
    const uint32_t sbase = smem_u32(smem_raw);
    const int tid = threadIdx.x;
    const int wid = tid >> 5;
    const int lane = tid & 31;
    const int warp_m = wid & 1;    // 2 warps along M (64 rows each)
    const int warp_n = wid >> 1;   // 2 warps along N (64 cols each)

    // tile raster for L2 reuse (GROUP_M=16 over 32 n-tiles, 512 tiles/group)
    auto tile_ptrs = [&](int t, const __half*& pA, const __half*& pB, float*& pO) {
        int group = t >> 9;
        int rem = t & 511;
        int mt_blk = group * 16 + (rem & 15);
        int nt_blk = rem >> 4;
        size_t m0 = (size_t)mt_blk * BM;
        size_t n0 = (size_t)nt_blk * BN;
        pA = g_Xh + m0 * DK;
        pB = g_Wh + n0 * DK;
        pO = out + m0 * DN + n0;
    };

    auto load_stage = [&](int s, const __half* pA, const __half* pB, int kc) {
        uint32_t base = sbase + s * STAGE_BYTES;
        int k0 = kc * BK;
#pragma unroll
        for (int j = 0; j < 4; j++) {          // A then B: 128 rows x 4 chunks each
            int i = tid + j * 128;             // 0..511
            int row = i >> 2;
            int c = i & 3;
            uint32_t off = (uint32_t)(row * 64 + ((c ^ ((row >> 1) & 3)) * 16));
            cp_async16(base + off, pA + (size_t)row * DK + k0 + c * 8);
            cp_async16(base + TILE_A_BYTES + off, pB + (size_t)row * DK + k0 + c * 8);
        }
    };

    // per-thread ldmatrix address components (xor term constant across mt/h
    // tiles: tile strides are 16 rows, and (16>>1)&3 == 0)
    const int rowA = warp_m * 64 + (lane & 15);
    const int xa = (rowA >> 1) & 3;
    const uint32_t offA = (uint32_t)(rowA * 64);
    const int rowB = warp_n * 64 + ((lane >> 4) << 3) + (lane & 7);
    const int xb = (rowB >> 1) & 3;
    const uint32_t offB = (uint32_t)(rowB * 64);

    float acc[4][8][4];
#pragma unroll
    for (int mt = 0; mt < 4; mt++)
#pragma unroll
        for (int nt = 0; nt < 8; nt++)
#pragma unroll
            for (int r = 0; r < 4; r++) acc[mt][nt][r] = 0.f;

    int t = blockIdx.x;
    const __half *pA, *pB;
    float* pO;
    tile_ptrs(t, pA, pB, pO);

    // stage wrap counters, continuous across tiles (128 % 7 != 0)
    int sl = 0;  // stage for the next load
    int sc = 0;  // stage to consume this iteration

    // prologue: chunks 0..STAGES-2 of first tile
#pragma unroll
    for (int s = 0; s < STAGES - 1; s++) {
        load_stage(sl, pA, pB, s);
        cp_commit();
        sl = (sl + 1 == STAGES) ? 0 : sl + 1;
    }

    while (true) {
        const int t_next = t + GRID_P;
        const bool have_next = (t_next < NTILES);
        const __half *pAn = pA, *pBn = pB;
        float* pOn = pO;
        if (have_next) tile_ptrs(t_next, pAn, pBn, pOn);

        for (int it = 0; it < NITER; it++) {
            cp_wait<STAGES - 2>();
            __syncthreads();

            // continuous load stream: tail iterations prefetch next tile
            int kc = it + STAGES - 1;
            if (kc < NITER) load_stage(sl, pA, pB, kc);
            else if (have_next) load_stage(sl, pAn, pBn, kc - NITER);
            cp_commit();
            sl = (sl + 1 == STAGES) ? 0 : sl + 1;

            const uint32_t stA = sbase + sc * STAGE_BYTES;
            const uint32_t stB = stA + TILE_A_BYTES;
            sc = (sc + 1 == STAGES) ? 0 : sc + 1;
#pragma unroll
            for (int s16 = 0; s16 < 2; s16++) {
                uint32_t a[4][4];
                uint32_t b[8][2];
                const int cA = (s16 * 2 + (lane >> 4)) ^ xa;
#pragma unroll
                for (int mt = 0; mt < 4; mt++)
                    ldmx4(a[mt], stA + offA + mt * 1024 + cA * 16);
                const int cB = (s16 * 2 + ((lane >> 3) & 1)) ^ xb;
#pragma unroll
                for (int h = 0; h < 4; h++) {  // 4 x (16 rows of B) = 64 cols
                    uint32_t r[4];
                    ldmx4(r, stB + offB + h * 1024 + cB * 16);
                    b[h * 2 + 0][0] = r[0]; b[h * 2 + 0][1] = r[1];
                    b[h * 2 + 1][0] = r[2]; b[h * 2 + 1][1] = r[3];
                }
#pragma unroll
                for (int mt = 0; mt < 4; mt++)
#pragma unroll
                    for (int nt = 0; nt < 8; nt++)
                        mma16816(acc[mt][nt], a[mt], b[nt]);
            }
        }

        // epilogue for tile t: streaming stores (write-once; evict-first so
        // out lines don't displace A/B operand tiles in L2). Overlaps next
        // tile's pipeline.
#pragma unroll
        for (int mt = 0; mt < 4; mt++) {
            int r0 = warp_m * 64 + mt * 16 + (lane >> 2);
#pragma unroll
            for (int nt = 0; nt < 8; nt++) {
                int col = warp_n * 64 + nt * 8 + (lane & 3) * 2;
                __stcs((float2*)(pO + (size_t)r0 * DN + col),
                       make_float2(acc[mt][nt][0], acc[mt][nt][1]));
                __stcs((float2*)(pO + (size_t)(r0 + 8) * DN + col),
                       make_float2(acc[mt][nt][2], acc[mt][nt][3]));
                acc[mt][nt][0] = 0.f; acc[mt][nt][1] = 0.f;
                acc[mt][nt][2] = 0.f; acc[mt][nt][3] = 0.f;
            }
        }

        if (!have_next) break;
        t = t_next; pA = pAn; pB = pBn; pO = pOn;
    }
}

// ------------------------------ launch -------------------------------------
extern "C" void kernel_launch(void* const* d_in, const int* in_sizes, int n_in,
                              void* d_out, int out_size) {
    (void)in_sizes; (void)n_in; (void)out_size;
    const float* x       = (const float*)d_in[0];
    const float* signs   = (const float*)d_in[1];
    const float* ps      = (const float*)d_in[2];
    const float* routing = (const float*)d_in[3];
    float* out = (float*)d_out;

    cudaFuncSetAttribute(gemm_kernel, cudaFuncAttributeMaxDynamicSharedMemorySize,
                         SMEM_TOTAL);

    prep_kernel<<<PREP_BLOCKS, 256>>>(x, signs, ps, routing);
    gemm_kernel<<<GRID_P, 128, SMEM_TOTAL>>>(out);
}